// round 7
// baseline (speedup 1.0000x reference)
#include <cuda_runtime.h>
#include <cuda_bf16.h>
#include <cstdint>

// Problem constants
#define B_DIM 4
#define T_DIM 2048
#define C_DIM 1024
#define H_DIM 16
#define DH    64
#define NTOK  8192
#define QKV_N 3072

// Static device scratch (no cudaMalloc allowed)
__device__ __nv_bfloat16 g_qkvhi[(size_t)NTOK * QKV_N];
__device__ __nv_bfloat16 g_qkvlo[(size_t)NTOK * QKV_N];
__device__ __nv_bfloat16 g_xh[(size_t)NTOK * C_DIM];
__device__ uint8_t       g_xpk[(size_t)NTOK * 2 * C_DIM];     // A-side: [Al8 | Ah8]
__device__ __nv_bfloat16 g_wqh[(size_t)QKV_N * C_DIM];
__device__ uint8_t       g_wqpk[(size_t)QKV_N * 2 * C_DIM];   // B-side: [Bh8 | Bl8]
__device__ __nv_bfloat16 g_woh[(size_t)C_DIM * C_DIM];
__device__ uint8_t       g_wopk[(size_t)C_DIM * 2 * C_DIM];   // B-side
__device__ __nv_bfloat16 g_ah[(size_t)NTOK * C_DIM];
__device__ uint8_t       g_apk[(size_t)NTOK * 2 * C_DIM];     // A-side

// ---------------------------------------------------------------------------
// Helpers (base sm_100: cp.async, ldmatrix, mma.sync bf16 + fp8)
// ---------------------------------------------------------------------------
static __device__ __forceinline__ uint32_t smem_u32(const void* p) {
    uint32_t a;
    asm("{ .reg .u64 t; cvta.to.shared.u64 t, %1; cvt.u32.u64 %0, t; }"
        : "=r"(a) : "l"(p));
    return a;
}
static __device__ __forceinline__ void cp_async16(uint32_t s, const void* g) {
    asm volatile("cp.async.ca.shared.global [%0], [%1], 16;" :: "r"(s), "l"(g));
}
static __device__ __forceinline__ void cp_commit() {
    asm volatile("cp.async.commit_group;" ::: "memory");
}
template <int N> static __device__ __forceinline__ void cp_wait() {
    asm volatile("cp.async.wait_group %0;" :: "n"(N) : "memory");
}
static __device__ __forceinline__ void ldsm4(uint32_t* r, uint32_t addr) {
    asm volatile("ldmatrix.sync.aligned.m8n8.x4.shared.b16 {%0,%1,%2,%3}, [%4];"
        : "=r"(r[0]), "=r"(r[1]), "=r"(r[2]), "=r"(r[3]) : "r"(addr));
}
static __device__ __forceinline__ void ldsm4t(uint32_t* r, uint32_t addr) {
    asm volatile("ldmatrix.sync.aligned.m8n8.x4.trans.shared.b16 {%0,%1,%2,%3}, [%4];"
        : "=r"(r[0]), "=r"(r[1]), "=r"(r[2]), "=r"(r[3]) : "r"(addr));
}
static __device__ __forceinline__ void mma16816(float* c, const uint32_t* a,
                                                const uint32_t* b) {
    asm("mma.sync.aligned.m16n8k16.row.col.f32.bf16.bf16.f32 "
        "{%0,%1,%2,%3}, {%4,%5,%6,%7}, {%8,%9}, {%0,%1,%2,%3};"
        : "+f"(c[0]), "+f"(c[1]), "+f"(c[2]), "+f"(c[3])
        : "r"(a[0]), "r"(a[1]), "r"(a[2]), "r"(a[3]), "r"(b[0]), "r"(b[1]));
}
// fp8 e4m3 MMA, k32 — byte-identical fragment geometry to bf16 k16
static __device__ __forceinline__ void mma16832q(float* c, const uint32_t* a,
                                                 const uint32_t* b) {
    asm("mma.sync.aligned.m16n8k32.row.col.f32.e4m3.e4m3.f32 "
        "{%0,%1,%2,%3}, {%4,%5,%6,%7}, {%8,%9}, {%0,%1,%2,%3};"
        : "+f"(c[0]), "+f"(c[1]), "+f"(c[2]), "+f"(c[3])
        : "r"(a[0]), "r"(a[1]), "r"(a[2]), "r"(a[3]), "r"(b[0]), "r"(b[1]));
}
// Split two fp32 into packed bf16x2 hi + bf16x2 lo (lo = residual)
static __device__ __forceinline__ void split2(float a, float b,
                                              uint32_t& hi, uint32_t& lo) {
    __nv_bfloat16 ha = __float2bfloat16(a), hb = __float2bfloat16(b);
    float ra = a - __bfloat162float(ha);
    float rb = b - __bfloat162float(hb);
    __nv_bfloat162 H(ha, hb);
    __nv_bfloat162 L(__float2bfloat16(ra), __float2bfloat16(rb));
    hi = *(uint32_t*)&H; lo = *(uint32_t*)&L;
}
// Pack 2 floats to 2 e4m3 bytes: byte0 = e4m3(f0), byte1 = e4m3(f1)
static __device__ __forceinline__ uint16_t e4m3pk2(float f0, float f1) {
    uint16_t r;
    asm("cvt.rn.satfinite.e4m3x2.f32 %0, %1, %2;" : "=h"(r) : "f"(f1), "f"(f0));
    return r;
}

// ---------------------------------------------------------------------------
// Split fp32 -> bf16 hi + fp8 pack (hi8, lo8 scaled) in one pass.
// pack row layout: 2K bytes; hi8 seg at hi_off, lo8 seg at lo_off.
// ---------------------------------------------------------------------------
__global__ __launch_bounds__(256) void split8_kernel(
    const float* __restrict__ src, __nv_bfloat16* __restrict__ hib,
    uint8_t* __restrict__ pack, int K, int lo_off, int hi_off,
    float hs, float ls, int n4)
{
    int i = blockIdx.x * blockDim.x + threadIdx.x;
    if (i >= n4) return;
    int e = i * 4;
    int row = e / K;
    int k = e - row * K;
    float4 v = ((const float4*)src)[i];

    __nv_bfloat16 h0 = __float2bfloat16(v.x), h1 = __float2bfloat16(v.y);
    __nv_bfloat16 h2 = __float2bfloat16(v.z), h3 = __float2bfloat16(v.w);
    float f0 = __bfloat162float(h0), f1 = __bfloat162float(h1);
    float f2 = __bfloat162float(h2), f3 = __bfloat162float(h3);

    __nv_bfloat162 H0(h0, h1), H1(h2, h3);
    *(uint32_t*)(hib + e)     = *(uint32_t*)&H0;
    *(uint32_t*)(hib + e + 2) = *(uint32_t*)&H1;

    uint32_t hi4 = (uint32_t)e4m3pk2(f0 * hs, f1 * hs)
                 | ((uint32_t)e4m3pk2(f2 * hs, f3 * hs) << 16);
    uint32_t lo4 = (uint32_t)e4m3pk2((v.x - f0) * ls, (v.y - f1) * ls)
                 | ((uint32_t)e4m3pk2((v.z - f2) * ls, (v.w - f3) * ls) << 16);
    size_t base = (size_t)row * 2 * K;
    *(uint32_t*)(pack + base + hi_off + k) = hi4;
    *(uint32_t*)(pack + base + lo_off + k) = lo4;
}

// ---------------------------------------------------------------------------
// Hybrid GEMM: C = Ah·Bh (bf16) + cross terms via ONE fp8 GEMM of depth 2K.
//   phase Q (chunks 0..nq-1):  acc = [Al8|Ah8]·[Bh8|Bl8]   (scale 2^18)
//   rescale acc ×= descale
//   phase H (chunks nq..2nq-1): acc += Ah·Bh (bf16)
// 4-stage cp.async pipeline, chunk = 2 tiles x 128 rows x 64B.
// ---------------------------------------------------------------------------
#define TSTR    80
#define TILE1   (128 * TSTR)
#define STG     (2 * TILE1)
#define G_SMEM  (4 * STG)

__global__ __launch_bounds__(256, 2) void gemm_hilo_kernel(
    const __nv_bfloat16* __restrict__ Ah, const uint8_t* __restrict__ Apk,
    const __nv_bfloat16* __restrict__ Bh, const uint8_t* __restrict__ Bpk,
    const float* __restrict__ bias, float* __restrict__ Cf,
    __nv_bfloat16* __restrict__ Chi, __nv_bfloat16* __restrict__ Clo,
    int M, int N, int K, float descale)
{
    extern __shared__ char smraw[];
    const uint32_t sb = smem_u32(smraw);

    const int tid  = threadIdx.x;
    const int lane = tid & 31;
    const int wid  = tid >> 5;
    const int wm   = wid >> 1;
    const int wn   = wid & 1;
    const int m0 = blockIdx.y * 128;
    const int n0 = blockIdx.x * 128;

    const int RB  = 2 * K;        // bytes per row (all 4 operand arrays)
    const int nq  = RB / 64;      // fp8 chunks
    const int nch = 2 * nq;

    const uint32_t a_row = lane & 15;
    const uint32_t a_kof = (lane >> 4) << 4;
    const uint32_t b_row = (lane & 7) | (((lane >> 4) & 1) << 3);
    const uint32_t b_kof = ((lane >> 3) & 1) << 4;

    float acc[2][8][4];
    #pragma unroll
    for (int i = 0; i < 2; i++)
        #pragma unroll
        for (int j = 0; j < 8; j++)
            #pragma unroll
            for (int c = 0; c < 4; c++) acc[i][j][c] = 0.0f;

    auto loader = [&](int c) {
        const int st = c & 3;
        const char* bA = (c < nq) ? (const char*)Apk : (const char*)Ah;
        const char* bB = (c < nq) ? (const char*)Bpk : (const char*)Bh;
        const int off = (c % nq) * 64;
        #pragma unroll
        for (int it = 0; it < 4; it++) {
            int idx = tid + it * 256;
            int t   = idx >> 9;            // 0 = A, 1 = B
            int w2  = idx & 511;
            int row = w2 >> 2;
            int seg = w2 & 3;
            const char* gp = (t ? bB + (size_t)(n0 + row) * RB
                                : bA + (size_t)(m0 + row) * RB) + off + seg * 16;
            cp_async16(sb + st * STG + t * TILE1 + row * TSTR + seg * 16, gp);
        }
    };

    loader(0); cp_commit();
    loader(1); cp_commit();
    loader(2); cp_commit();

    for (int c = 0; c < nch; c++) {
        cp_wait<2>();          // group c complete (this thread)
        __syncthreads();       // all threads' group c visible; compute(c-1) done
        if (c + 3 < nch) loader(c + 3);
        cp_commit();           // keep group arithmetic uniform (may be empty)

        if (c == nq) {         // cross sums done -> rescale before bf16 phase
            #pragma unroll
            for (int i = 0; i < 2; i++)
                #pragma unroll
                for (int j = 0; j < 8; j++)
                    #pragma unroll
                    for (int cc = 0; cc < 4; cc++) acc[i][j][cc] *= descale;
        }

        const uint32_t bufA = sb + (c & 3) * STG;
        const uint32_t bufB = bufA + TILE1;
        const bool q = (c < nq);

        #pragma unroll
        for (int ks = 0; ks < 2; ks++) {
            const uint32_t kb = ks * 32;
            uint32_t ah_[2][4], bb[4][4];
            #pragma unroll
            for (int mi = 0; mi < 2; mi++)
                ldsm4(ah_[mi], bufA + (wm * 32 + mi * 16 + a_row) * TSTR + kb + a_kof);
            #pragma unroll
            for (int njp = 0; njp < 4; njp++)
                ldsm4(bb[njp], bufB + (wn * 64 + njp * 16 + b_row) * TSTR + kb + b_kof);

            if (q) {
                #pragma unroll
                for (int njp = 0; njp < 4; njp++)
                    #pragma unroll
                    for (int mi = 0; mi < 2; mi++) {
                        mma16832q(acc[mi][2 * njp],     ah_[mi], bb[njp]);
                        mma16832q(acc[mi][2 * njp + 1], ah_[mi], bb[njp] + 2);
                    }
            } else {
                #pragma unroll
                for (int njp = 0; njp < 4; njp++)
                    #pragma unroll
                    for (int mi = 0; mi < 2; mi++) {
                        mma16816(acc[mi][2 * njp],     ah_[mi], bb[njp]);
                        mma16816(acc[mi][2 * njp + 1], ah_[mi], bb[njp] + 2);
                    }
            }
        }
    }

    // Epilogue: bias add; fp32 out (Cf) or bf16 hi/lo split (Chi/Clo)
    #pragma unroll
    for (int mi = 0; mi < 2; mi++) {
        int row = m0 + wm * 32 + mi * 16 + (lane >> 2);
        #pragma unroll
        for (int nj = 0; nj < 8; nj++) {
            int col = n0 + wn * 64 + nj * 8 + (lane & 3) * 2;
            float bx = bias[col], by = bias[col + 1];
            float v00 = acc[mi][nj][0] + bx, v01 = acc[mi][nj][1] + by;
            float v10 = acc[mi][nj][2] + bx, v11 = acc[mi][nj][3] + by;
            if (Cf) {
                *(float2*)(Cf + (size_t)row * N + col) = make_float2(v00, v01);
                *(float2*)(Cf + (size_t)(row + 8) * N + col) = make_float2(v10, v11);
            } else {
                uint32_t hi, lo;
                split2(v00, v01, hi, lo);
                *(uint32_t*)(Chi + (size_t)row * N + col) = hi;
                *(uint32_t*)(Clo + (size_t)row * N + col) = lo;
                split2(v10, v11, hi, lo);
                *(uint32_t*)(Chi + (size_t)(row + 8) * N + col) = hi;
                *(uint32_t*)(Clo + (size_t)(row + 8) * N + col) = lo;
            }
        }
    }
}

// ---------------------------------------------------------------------------
// Tensor-core causal flash attention (bf16x3 S and PV), unchanged from R6
// except the epilogue now emits bf16-hi + fp8 A-side pack for the out-proj.
// ---------------------------------------------------------------------------
#define ASTR   144
#define AQH    0
#define AQL    18432
#define AKH    36864
#define AKL    55296
#define AVH    73728
#define AVL    92160
#define AKVB   9216
#define A_SMEM 110592

__global__ __launch_bounds__(256, 2) void attn_mma_kernel(
    const __nv_bfloat16* __restrict__ qhi, const __nv_bfloat16* __restrict__ qlo,
    __nv_bfloat16* __restrict__ ohi, uint8_t* __restrict__ opk)
{
    extern __shared__ char smraw[];
    const uint32_t sb = smem_u32(smraw);

    const int b = blockIdx.z, h = blockIdx.y;
    const int q0 = ((int)gridDim.x - 1 - (int)blockIdx.x) * 128;
    const int tid = threadIdx.x, lane = tid & 31, w = tid >> 5;
    const int g = lane >> 2, t4 = lane & 3;

    #pragma unroll
    for (int it = 0; it < 8; it++) {
        int idx = tid + it * 256;
        int hl  = idx >> 10;
        int wq  = idx & 1023;
        int row = wq >> 3, seg = wq & 7;
        const __nv_bfloat16* gp = (hl ? qlo : qhi)
            + (size_t)(b * T_DIM + q0 + row) * QKV_N + h * DH + seg * 8;
        cp_async16(sb + (hl ? AQL : AQH) + row * ASTR + seg * 16, gp);
    }

    auto load_kv = [&](int t, int buf) {
        const int k0 = t * 64;
        #pragma unroll
        for (int it = 0; it < 8; it++) {
            int idx = tid + it * 256;
            int which = idx >> 9;
            int wq  = idx & 511;
            int row = wq >> 3, seg = wq & 7;
            size_t goff = (size_t)(b * T_DIM + k0 + row) * QKV_N + h * DH + seg * 8;
            const __nv_bfloat16* gp;
            uint32_t base;
            if (which == 0)      { gp = qhi + goff + C_DIM;     base = AKH; }
            else if (which == 1) { gp = qlo + goff + C_DIM;     base = AKL; }
            else if (which == 2) { gp = qhi + goff + 2 * C_DIM; base = AVH; }
            else                 { gp = qlo + goff + 2 * C_DIM; base = AVL; }
            cp_async16(sb + base + buf * AKVB + row * ASTR + seg * 16, gp);
        }
    };

    load_kv(0, 0);
    cp_commit();

    float O[8][4];
    #pragma unroll
    for (int j = 0; j < 8; j++)
        #pragma unroll
        for (int c = 0; c < 4; c++) O[j][c] = 0.0f;
    float m0 = -1e30f, m1 = -1e30f, l0 = 0.0f, l1 = 0.0f;

    const uint32_t a_off = (uint32_t)(w * 16 + (lane & 15)) * ASTR + ((lane >> 4) << 4);
    const uint32_t b_row = (uint32_t)((lane & 7) | (((lane >> 4) & 1) << 3));
    const uint32_t b_kof = ((lane >> 3) & 1) << 4;
    const uint32_t v_off = (uint32_t)(lane & 15) * ASTR + ((lane >> 4) << 4);

    const int ntiles = (q0 >> 6) + 2;
    for (int t = 0; t < ntiles; t++) {
        if (t + 1 < ntiles) { load_kv(t + 1, (t + 1) & 1); cp_commit(); cp_wait<1>(); }
        else                { cp_wait<0>(); }
        __syncthreads();
        const uint32_t kb = (t & 1) * AKVB;

        float S[8][4];
        #pragma unroll
        for (int j = 0; j < 8; j++)
            #pragma unroll
            for (int c = 0; c < 4; c++) S[j][c] = 0.0f;

        #pragma unroll
        for (int ks = 0; ks < 4; ks++) {
            uint32_t qh[4], ql[4], kk[4][4];
            ldsm4(qh, sb + AQH + a_off + ks * 32);
            ldsm4(ql, sb + AQL + a_off + ks * 32);
            #pragma unroll
            for (int jg = 0; jg < 4; jg++)
                ldsm4(kk[jg], sb + AKH + kb + (jg * 16 + b_row) * ASTR + ks * 32 + b_kof);
            #pragma unroll
            for (int jg = 0; jg < 4; jg++) {
                mma16816(S[2 * jg],     qh, kk[jg]);
                mma16816(S[2 * jg + 1], qh, kk[jg] + 2);
            }
            #pragma unroll
            for (int jg = 0; jg < 4; jg++) {
                mma16816(S[2 * jg],     ql, kk[jg]);
                mma16816(S[2 * jg + 1], ql, kk[jg] + 2);
            }
            #pragma unroll
            for (int jg = 0; jg < 4; jg++)
                ldsm4(kk[jg], sb + AKL + kb + (jg * 16 + b_row) * ASTR + ks * 32 + b_kof);
            #pragma unroll
            for (int jg = 0; jg < 4; jg++) {
                mma16816(S[2 * jg],     qh, kk[jg]);
                mma16816(S[2 * jg + 1], qh, kk[jg] + 2);
            }
        }

        const int k0 = t * 64;
        const int qw = q0 + w * 16;
        #pragma unroll
        for (int j = 0; j < 8; j++)
            #pragma unroll
            for (int c = 0; c < 4; c++) S[j][c] *= 0.125f;
        if (k0 + 64 > qw) {
            const int r0 = qw + g, r1 = qw + g + 8;
            #pragma unroll
            for (int j = 0; j < 8; j++) {
                int key = k0 + j * 8 + t4 * 2;
                if (key     > r0) S[j][0] = -1e30f;
                if (key + 1 > r0) S[j][1] = -1e30f;
                if (key     > r1) S[j][2] = -1e30f;
                if (key + 1 > r1) S[j][3] = -1e30f;
            }
        }

        float mx0 = -1e30f, mx1 = -1e30f;
        #pragma unroll
        for (int j = 0; j < 8; j++) {
            mx0 = fmaxf(mx0, fmaxf(S[j][0], S[j][1]));
            mx1 = fmaxf(mx1, fmaxf(S[j][2], S[j][3]));
        }
        mx0 = fmaxf(mx0, __shfl_xor_sync(0xffffffffu, mx0, 1));
        mx0 = fmaxf(mx0, __shfl_xor_sync(0xffffffffu, mx0, 2));
        mx1 = fmaxf(mx1, __shfl_xor_sync(0xffffffffu, mx1, 1));
        mx1 = fmaxf(mx1, __shfl_xor_sync(0xffffffffu, mx1, 2));
        float nm0 = fmaxf(m0, mx0), nm1 = fmaxf(m1, mx1);
        float c0 = __expf(m0 - nm0), c1 = __expf(m1 - nm1);
        float s0 = 0.0f, s1 = 0.0f;
        #pragma unroll
        for (int j = 0; j < 8; j++) {
            S[j][0] = __expf(S[j][0] - nm0); s0 += S[j][0];
            S[j][1] = __expf(S[j][1] - nm0); s0 += S[j][1];
            S[j][2] = __expf(S[j][2] - nm1); s1 += S[j][2];
            S[j][3] = __expf(S[j][3] - nm1); s1 += S[j][3];
        }
        s0 += __shfl_xor_sync(0xffffffffu, s0, 1);
        s0 += __shfl_xor_sync(0xffffffffu, s0, 2);
        s1 += __shfl_xor_sync(0xffffffffu, s1, 1);
        s1 += __shfl_xor_sync(0xffffffffu, s1, 2);
        l0 = l0 * c0 + s0; l1 = l1 * c1 + s1;
        m0 = nm0; m1 = nm1;
        #pragma unroll
        for (int j = 0; j < 8; j++) {
            O[j][0] *= c0; O[j][1] *= c0;
            O[j][2] *= c1; O[j][3] *= c1;
        }

        uint32_t Ph[4][4], Pl[4][4];
        #pragma unroll
        for (int ks = 0; ks < 4; ks++) {
            split2(S[2 * ks][0],     S[2 * ks][1],     Ph[ks][0], Pl[ks][0]);
            split2(S[2 * ks][2],     S[2 * ks][3],     Ph[ks][1], Pl[ks][1]);
            split2(S[2 * ks + 1][0], S[2 * ks + 1][1], Ph[ks][2], Pl[ks][2]);
            split2(S[2 * ks + 1][2], S[2 * ks + 1][3], Ph[ks][3], Pl[ks][3]);
        }

        #pragma unroll
        for (int ks = 0; ks < 4; ks++) {
            uint32_t vv[4][4];
            #pragma unroll
            for (int db = 0; db < 4; db++)
                ldsm4t(vv[db], sb + AVH + kb + (uint32_t)ks * 16 * ASTR + v_off + db * 32);
            #pragma unroll
            for (int db = 0; db < 4; db++) {
                mma16816(O[2 * db],     Ph[ks], vv[db]);
                mma16816(O[2 * db + 1], Ph[ks], vv[db] + 2);
            }
            #pragma unroll
            for (int db = 0; db < 4; db++) {
                mma16816(O[2 * db],     Pl[ks], vv[db]);
                mma16816(O[2 * db + 1], Pl[ks], vv[db] + 2);
            }
            #pragma unroll
            for (int db = 0; db < 4; db++)
                ldsm4t(vv[db], sb + AVL + kb + (uint32_t)ks * 16 * ASTR + v_off + db * 32);
            #pragma unroll
            for (int db = 0; db < 4; db++) {
                mma16816(O[2 * db],     Ph[ks], vv[db]);
                mma16816(O[2 * db + 1], Ph[ks], vv[db] + 2);
            }
        }
        __syncthreads();
    }

    // ---- epilogue: normalize; emit bf16-hi + fp8 A-side pack [lo8 | hi8] ----
    const float inv0 = 1.0f / l0, inv1 = 1.0f / l1;
    const int tok0 = b * T_DIM + q0 + w * 16 + g;
    const size_t r0 = (size_t)tok0 * C_DIM + h * DH;
    const size_t r1 = r0 + 8 * C_DIM;
    const size_t p0 = (size_t)tok0 * (2 * C_DIM) + h * DH;
    const size_t p1 = p0 + 8 * (2 * C_DIM);
    #pragma unroll
    for (int j = 0; j < 8; j++) {
        int col = j * 8 + t4 * 2;
        {
            float a0 = O[j][0] * inv0, a1 = O[j][1] * inv0;
            __nv_bfloat16 h0 = __float2bfloat16(a0), h1 = __float2bfloat16(a1);
            float f0 = __bfloat162float(h0), f1 = __bfloat162float(h1);
            __nv_bfloat162 H(h0, h1);
            *(uint32_t*)(ohi + r0 + col) = *(uint32_t*)&H;
            *(uint16_t*)(opk + p0 + C_DIM + col) = e4m3pk2(f0 * 4.0f, f1 * 4.0f);
            *(uint16_t*)(opk + p0 + col) = e4m3pk2((a0 - f0) * 2048.0f, (a1 - f1) * 2048.0f);
        }
        {
            float a0 = O[j][2] * inv1, a1 = O[j][3] * inv1;
            __nv_bfloat16 h0 = __float2bfloat16(a0), h1 = __float2bfloat16(a1);
            float f0 = __bfloat162float(h0), f1 = __bfloat162float(h1);
            __nv_bfloat162 H(h0, h1);
            *(uint32_t*)(ohi + r1 + col) = *(uint32_t*)&H;
            *(uint16_t*)(opk + p1 + C_DIM + col) = e4m3pk2(f0 * 4.0f, f1 * 4.0f);
            *(uint16_t*)(opk + p1 + col) = e4m3pk2((a0 - f0) * 2048.0f, (a1 - f1) * 2048.0f);
        }
    }
}

// ---------------------------------------------------------------------------
// Launch
// ---------------------------------------------------------------------------
extern "C" void kernel_launch(void* const* d_in, const int* in_sizes, int n_in,
                              void* d_out, int out_size)
{
    const float* x    = (const float*)d_in[0];
    const float* Wqkv = (const float*)d_in[1];
    const float* bqkv = (const float*)d_in[2];
    const float* Wo   = (const float*)d_in[3];
    const float* bo   = (const float*)d_in[4];
    float* out = (float*)d_out;

    __nv_bfloat16 *qkvhi, *qkvlo, *xh, *wqh, *woh, *ah;
    uint8_t *xpk, *wqpk, *wopk, *apk;
    cudaGetSymbolAddress((void**)&qkvhi, g_qkvhi);
    cudaGetSymbolAddress((void**)&qkvlo, g_qkvlo);
    cudaGetSymbolAddress((void**)&xh,  g_xh);
    cudaGetSymbolAddress((void**)&xpk, g_xpk);
    cudaGetSymbolAddress((void**)&wqh, g_wqh);
    cudaGetSymbolAddress((void**)&wqpk, g_wqpk);
    cudaGetSymbolAddress((void**)&woh, g_woh);
    cudaGetSymbolAddress((void**)&wopk, g_wopk);
    cudaGetSymbolAddress((void**)&ah,  g_ah);
    cudaGetSymbolAddress((void**)&apk, g_apk);

    cudaFuncSetAttribute(gemm_hilo_kernel,
                         cudaFuncAttributeMaxDynamicSharedMemorySize, G_SMEM);
    cudaFuncSetAttribute(attn_mma_kernel,
                         cudaFuncAttributeMaxDynamicSharedMemorySize, A_SMEM);

    const float DS = 1.0f / 262144.0f;   // 2^-18

    // x: sigma~1  -> hi x4 (2^2), lo x2^11 ; A-side pack [lo | hi]
    split8_kernel<<<(NTOK * C_DIM / 4 + 255) / 256, 256>>>(
        x, xh, xpk, C_DIM, 0, C_DIM, 4.0f, 2048.0f, NTOK * C_DIM / 4);
    // W: sigma~1/32 -> hi x2^7, lo x2^16 ; B-side pack [hi | lo]
    split8_kernel<<<(QKV_N * C_DIM / 4 + 255) / 256, 256>>>(
        Wqkv, wqh, wqpk, C_DIM, C_DIM, 0, 128.0f, 65536.0f, QKV_N * C_DIM / 4);
    split8_kernel<<<(C_DIM * C_DIM / 4 + 255) / 256, 256>>>(
        Wo, woh, wopk, C_DIM, C_DIM, 0, 128.0f, 65536.0f, C_DIM * C_DIM / 4);

    // qkv (bf16 hi/lo) = x @ Wqkv^T + bqkv   (fp8 cross + bf16 hi)
    gemm_hilo_kernel<<<dim3(QKV_N / 128, NTOK / 128), 256, G_SMEM>>>(
        xh, xpk, wqh, wqpk, bqkv, nullptr, qkvhi, qkvlo, NTOK, QKV_N, C_DIM, DS);

    // attention -> bf16 hi + fp8 pack
    attn_mma_kernel<<<dim3(T_DIM / 128, H_DIM, B_DIM), 256, A_SMEM>>>(
        qkvhi, qkvlo, ah, apk);

    // out (fp32) = attn @ Wo^T + bo
    gemm_hilo_kernel<<<dim3(C_DIM / 128, NTOK / 128), 256, G_SMEM>>>(
        ah, apk, woh, wopk, bo, out, nullptr, nullptr, NTOK, C_DIM, C_DIM, DS);
}